// round 13
// baseline (speedup 1.0000x reference)
#include <cuda_runtime.h>
#include <cuda_bf16.h>
#include <stdint.h>

// ============================================================================
// VoxMLP: (1) trilinear gather of (g, grad g) with on-the-fly central diffs
//         (2) persistent weight-stationary 4-stage layer PIPELINE:
//             warp (s,c): layer s, col-block c (n32). Weights live in 64 regs
//             per warp. 16-pt tiles stream through mbarrier rings. Skip
//             connection handled as fp32 partial (stage0 computes FEAT*W3B).
// Output layout (float32): [0,B) = c0 ; [B,4B) = grad (B,3) ; [4B,7B) = rot
// ============================================================================

#define GD   256
#define SX   65536
#define SY   256

// ---------------------------------------------------------------------------
// Kernel 1: gather + gradient (known-good, ~104us)
// ---------------------------------------------------------------------------
__global__ void __launch_bounds__(256) gather_kernel(
    const float* __restrict__ x, const float* __restrict__ grid,
    float* __restrict__ out, int B)
{
    int p = blockIdx.x * blockDim.x + threadIdx.x;
    if (p >= B) return;

    float px = x[3*p+0], py = x[3*p+1], pz = x[3*p+2];
    float fx = (px + 1.0f) * 127.5f;
    float fy = (py + 1.0f) * 127.5f;
    float fz = (pz + 1.0f) * 127.5f;
    float x0f = floorf(fx), y0f = floorf(fy), z0f = floorf(fz);
    float xd = fx - x0f, yd = fy - y0f, zd = fz - z0f;

    int ix0 = min(max((int)x0f, 0), GD-1);
    int ix1 = min(max((int)x0f + 1, 0), GD-1);
    int iy0 = min(max((int)y0f, 0), GD-1);
    int iy1 = min(max((int)y0f + 1, 0), GD-1);
    int iz0 = min(max((int)z0f, 0), GD-1);
    int iz1 = min(max((int)z0f + 1, 0), GD-1);

    int pvx = max(ix0-1, 0), nxx = min(ix1+1, GD-1);
    int pvy = max(iy0-1, 0), nxy = min(iy1+1, GD-1);
    int pvz = max(iz0-1, 0), nxz = min(iz1+1, GD-1);

    int bx0 = ix0*SX, bx1 = ix1*SX;
    int by0 = iy0*SY, by1 = iy1*SY;
    int bpx = pvx*SX, bnx = nxx*SX;
    int bpy = pvy*SY, bny = nxy*SY;

    float v000 = __ldg(grid + bx0 + by0 + iz0);
    float v001 = __ldg(grid + bx0 + by0 + iz1);
    float v010 = __ldg(grid + bx0 + by1 + iz0);
    float v011 = __ldg(grid + bx0 + by1 + iz1);
    float v100 = __ldg(grid + bx1 + by0 + iz0);
    float v101 = __ldg(grid + bx1 + by0 + iz1);
    float v110 = __ldg(grid + bx1 + by1 + iz0);
    float v111 = __ldg(grid + bx1 + by1 + iz1);

    float xm00 = __ldg(grid + bpx + by0 + iz0);
    float xm01 = __ldg(grid + bpx + by0 + iz1);
    float xm10 = __ldg(grid + bpx + by1 + iz0);
    float xm11 = __ldg(grid + bpx + by1 + iz1);
    float xp00 = __ldg(grid + bnx + by0 + iz0);
    float xp01 = __ldg(grid + bnx + by0 + iz1);
    float xp10 = __ldg(grid + bnx + by1 + iz0);
    float xp11 = __ldg(grid + bnx + by1 + iz1);

    float ym00 = __ldg(grid + bx0 + bpy + iz0);
    float ym01 = __ldg(grid + bx0 + bpy + iz1);
    float ym10 = __ldg(grid + bx1 + bpy + iz0);
    float ym11 = __ldg(grid + bx1 + bpy + iz1);
    float yp00 = __ldg(grid + bx0 + bny + iz0);
    float yp01 = __ldg(grid + bx0 + bny + iz1);
    float yp10 = __ldg(grid + bx1 + bny + iz0);
    float yp11 = __ldg(grid + bx1 + bny + iz1);

    float zm00 = __ldg(grid + bx0 + by0 + pvz);
    float zm01 = __ldg(grid + bx0 + by1 + pvz);
    float zm10 = __ldg(grid + bx1 + by0 + pvz);
    float zm11 = __ldg(grid + bx1 + by1 + pvz);
    float zp00 = __ldg(grid + bx0 + by0 + nxz);
    float zp01 = __ldg(grid + bx0 + by1 + nxz);
    float zp10 = __ldg(grid + bx1 + by0 + nxz);
    float zp11 = __ldg(grid + bx1 + by1 + nxz);

    const float i2 = 63.75f;

    float dx000 = (v100 - xm00)*i2, dx001 = (v101 - xm01)*i2;
    float dx010 = (v110 - xm10)*i2, dx011 = (v111 - xm11)*i2;
    float dx100 = (xp00 - v000)*i2, dx101 = (xp01 - v001)*i2;
    float dx110 = (xp10 - v010)*i2, dx111 = (xp11 - v011)*i2;

    float dy000 = (v010 - ym00)*i2, dy001 = (v011 - ym01)*i2;
    float dy100 = (v110 - ym10)*i2, dy101 = (v111 - ym11)*i2;
    float dy010 = (yp00 - v000)*i2, dy011 = (yp01 - v001)*i2;
    float dy110 = (yp10 - v100)*i2, dy111 = (yp11 - v101)*i2;

    float dz000 = (v001 - zm00)*i2, dz010 = (v011 - zm01)*i2;
    float dz100 = (v101 - zm10)*i2, dz110 = (v111 - zm11)*i2;
    float dz001 = (zp00 - v000)*i2, dz011 = (zp01 - v010)*i2;
    float dz101 = (zp10 - v100)*i2, dz111 = (zp11 - v110)*i2;

    float xw0 = 1.0f - xd, yw0 = 1.0f - yd, zw0 = 1.0f - zd;
    float w000 = xw0*yw0*zw0, w001 = xw0*yw0*zd;
    float w010 = xw0*yd *zw0, w011 = xw0*yd *zd;
    float w100 = xd *yw0*zw0, w101 = xd *yw0*zd;
    float w110 = xd *yd *zw0, w111 = xd *yd *zd;

    float c0 = w000*v000 + w001*v001 + w010*v010 + w011*v011
             + w100*v100 + w101*v101 + w110*v110 + w111*v111;
    float gx = w000*dx000 + w001*dx001 + w010*dx010 + w011*dx011
             + w100*dx100 + w101*dx101 + w110*dx110 + w111*dx111;
    float gy = w000*dy000 + w001*dy001 + w010*dy010 + w011*dy011
             + w100*dy100 + w101*dy101 + w110*dy110 + w111*dy111;
    float gz = w000*dz000 + w001*dz001 + w010*dz010 + w011*dz011
             + w100*dz100 + w101*dz101 + w110*dz110 + w111*dz111;

    out[p]         = c0;
    out[B + 3*p+0] = gx;
    out[B + 3*p+1] = gy;
    out[B + 3*p+2] = gz;
}

// ---------------------------------------------------------------------------
// Kernel 2: weight-stationary 4-stage pipeline, 512 threads
// ---------------------------------------------------------------------------
#define PW0  144    // staging pitch W0t: 72 bf16/row
#define PW1  272    // staging pitch W1t/W2t
#define PW3  400    // staging pitch W3t
#define PH   272    // H ring slot pitch (16 rows)
#define OFF_W0   0
#define OFF_W1   18432
#define OFF_W2   53248
#define OFF_W3   88064      // staging ends 139264
// rings (overlap staging; used after preload + syncthreads)
#define OFF_H0   0          // 2 slots x 4352
#define OFF_H1   8704
#define OFF_H2   17408
#define OFF_D3   26112      // 10 slots x 8192 -> ends 108032
#define OFF_FEAT 108032     // 16 x 144 = 2304
#define HSLOT    4352
#define D3SLOT   8192
#define D3DEPTH  10
// persistent
#define OFF_BIAS 139264     // 4 x 128 f32
#define OFF_WO   141312     // 128 x 3 f32
#define OFF_BO   142848
#define OFF_RED  142880     // 16 rows x 4 c x 3 f32 = 768
#define OFF_MB   143648     // mbarriers (256 B)
#define SMEM_BYTES 143936

#define MB_HF(r, sl)  (smb + OFF_MB + (r)*32 + (sl)*16)
#define MB_HE(r, sl)  (smb + OFF_MB + (r)*32 + (sl)*16 + 8)
#define MB_DF(sl)     (smb + OFF_MB + 96 + (sl)*16)
#define MB_DE(sl)     (smb + OFF_MB + 96 + (sl)*16 + 8)

#define MBAR_INIT(mb, cnt) \
    asm volatile("mbarrier.init.shared.b64 [%0], %1;" \
                 :: "r"((uint32_t)(mb)), "r"((uint32_t)(cnt)) : "memory")
#define MBAR_ARRIVE(mb) \
    asm volatile("mbarrier.arrive.shared.b64 _, [%0];" \
                 :: "r"((uint32_t)(mb)) : "memory")
#define MBAR_WAIT(mb, ph) do { \
    uint32_t _m = (uint32_t)(mb), _p = (uint32_t)(ph), _d; \
    asm volatile( \
        "{\n\t.reg .pred p;\n\t" \
        "mbarrier.try_wait.parity.acquire.cta.shared::cta.b64 p, [%1], %2;\n\t" \
        "selp.b32 %0, 1, 0, p;\n\t}" \
        : "=r"(_d) : "r"(_m), "r"(_p) : "memory"); \
    if (!_d) { \
        asm volatile( \
            "{\n\t.reg .pred P1;\n\t" \
            "WL_%=:\n\t" \
            "mbarrier.try_wait.parity.acquire.cta.shared::cta.b64 P1, [%0], %1, 0x989680;\n\t" \
            "@P1 bra.uni WD_%=;\n\t" \
            "bra.uni WL_%=;\n\t" \
            "WD_%=:\n\t}" \
            :: "r"(_m), "r"(_p) : "memory"); \
    } \
} while (0)

__device__ __forceinline__ void ldsm4(uint32_t& r0, uint32_t& r1,
                                      uint32_t& r2, uint32_t& r3, uint32_t a)
{
    asm volatile("ldmatrix.sync.aligned.m8n8.x4.shared.b16 {%0,%1,%2,%3}, [%4];"
                 : "=r"(r0), "=r"(r1), "=r"(r2), "=r"(r3) : "r"(a));
}
__device__ __forceinline__ void mma16(float* c,
    uint32_t a0, uint32_t a1, uint32_t a2, uint32_t a3,
    uint32_t b0, uint32_t b1)
{
    asm("mma.sync.aligned.m16n8k16.row.col.f32.bf16.bf16.f32 "
        "{%0,%1,%2,%3}, {%4,%5,%6,%7}, {%8,%9}, {%0,%1,%2,%3};"
        : "+f"(c[0]), "+f"(c[1]), "+f"(c[2]), "+f"(c[3])
        : "r"(a0), "r"(a1), "r"(a2), "r"(a3), "r"(b0), "r"(b1));
}

// epilogue: m16n32 acc -> bias+relu -> bf16 -> H slot
__device__ __forceinline__ void epiH(char* slot, const float* bias,
    float (&acc)[4][4], int lane, int ncol0)
{
    const int g = lane >> 2, q = lane & 3;
    char* o0 = slot + g * PH + 2*ncol0 + 4*q;
    #pragma unroll
    for (int nt = 0; nt < 4; nt++) {
        int n = ncol0 + nt*8 + 2*q;
        float bv0 = bias[n], bv1 = bias[n+1];
        float c0 = fmaxf(acc[nt][0] + bv0, 0.f);
        float c1 = fmaxf(acc[nt][1] + bv1, 0.f);
        float c2 = fmaxf(acc[nt][2] + bv0, 0.f);
        float c3 = fmaxf(acc[nt][3] + bv1, 0.f);
        uint32_t p01, p23;
        asm("cvt.rn.bf16x2.f32 %0, %1, %2;" : "=r"(p01) : "f"(c1), "f"(c0));
        asm("cvt.rn.bf16x2.f32 %0, %1, %2;" : "=r"(p23) : "f"(c3), "f"(c2));
        *(uint32_t*)(o0 + nt*16)         = p01;
        *(uint32_t*)(o0 + 8*PH + nt*16)  = p23;
    }
}

__global__ void __launch_bounds__(512, 1) mlp_kernel(
    const float* __restrict__ x,
    const float* __restrict__ w0, const float* __restrict__ b0,
    const float* __restrict__ w1, const float* __restrict__ b1,
    const float* __restrict__ w2, const float* __restrict__ b2,
    const float* __restrict__ w3, const float* __restrict__ b3,
    const float* __restrict__ wo, const float* __restrict__ bo,
    float* __restrict__ out, int B)
{
    extern __shared__ char sm[];
    const int t = threadIdx.x;

    // ---- stage weights (transposed bf16) + bias/wo into SMEM ----
    for (int i = t; i < 128*64; i += 512) {
        int n = i >> 6, k = i & 63;
        ((__nv_bfloat16*)(sm + OFF_W0 + n*PW0))[k] =
            (k < 63) ? __float2bfloat16(w0[k*128 + n]) : __float2bfloat16(0.f);
    }
    for (int i = t; i < 128*128; i += 512) {
        int n = i >> 7, k = i & 127;
        ((__nv_bfloat16*)(sm + OFF_W1 + n*PW1))[k] = __float2bfloat16(w1[k*128 + n]);
        ((__nv_bfloat16*)(sm + OFF_W2 + n*PW1))[k] = __float2bfloat16(w2[k*128 + n]);
    }
    for (int i = t; i < 128*192; i += 512) {
        int n = i / 192, k = i % 192;
        ((__nv_bfloat16*)(sm + OFF_W3 + n*PW3))[k] =
            (k < 191) ? __float2bfloat16(w3[k*128 + n]) : __float2bfloat16(0.f);
    }
    if (t < 128) {
        float* bb = (float*)(sm + OFF_BIAS);
        bb[t] = b0[t]; bb[128 + t] = b1[t]; bb[256 + t] = b2[t]; bb[384 + t] = b3[t];
        float* wos = (float*)(sm + OFF_WO);
        wos[3*t+0] = wo[3*t+0]; wos[3*t+1] = wo[3*t+1]; wos[3*t+2] = wo[3*t+2];
    }
    if (t < 3) ((float*)(sm + OFF_BO))[t] = bo[t];
    __syncthreads();

    const uint32_t smb = [&]{ uint32_t a;
        asm("{ .reg .u64 t; cvta.to.shared.u64 t, %1; cvt.u32.u64 %0, t; }"
            : "=r"(a) : "l"(sm)); return a; }();

    const int lane = t & 31, warp = t >> 5;
    const int s = warp >> 2, c = warp & 3;
    const int ncol0 = 32 * c;
    const int l7 = lane & 7, l8 = (lane >> 3) & 1, l16 = lane >> 4;

    // ---- preload weight fragments into registers (uniform shape wb[8][8]) --
    uint32_t wb[8][8];
    {
        #pragma unroll
        for (int i = 0; i < 8; i++) {
            uint32_t base;
            if (s == 0) {
                // i 0..3: W0 kstep i ; i 4..7: W3B (k128..191) kstep i-4
                if (i < 4)
                    base = smb + OFF_W0 + (uint32_t)(ncol0 + l7 + 8*l16)*PW0
                         + 16*l8 + i*32;
                else
                    base = smb + OFF_W3 + (uint32_t)(ncol0 + l7 + 8*l16)*PW3
                         + 256 + 16*l8 + (i-4)*32;
            } else if (s == 1) {
                base = smb + OFF_W1 + (uint32_t)(ncol0 + l7 + 8*l16)*PW1
                     + 16*l8 + i*32;
            } else if (s == 2) {
                base = smb + OFF_W2 + (uint32_t)(ncol0 + l7 + 8*l16)*PW1
                     + 16*l8 + i*32;
            } else {
                base = smb + OFF_W3 + (uint32_t)(ncol0 + l7 + 8*l16)*PW3
                     + 16*l8 + i*32;
            }
            ldsm4(wb[i][0], wb[i][1], wb[i][2], wb[i][3], base);
            ldsm4(wb[i][4], wb[i][5], wb[i][6], wb[i][7],
                  base + 16u*((s == 0) ? (i < 4 ? PW0 : PW3)
                            : (s == 3 ? PW3 : PW1)));
        }
    }
    __syncthreads();

    if (t == 0) {
        #pragma unroll
        for (int r = 0; r < 3; r++)
            #pragma unroll
            for (int sl = 0; sl < 2; sl++) {
                MBAR_INIT(MB_HF(r, sl), 4);
                MBAR_INIT(MB_HE(r, sl), 4);
            }
        #pragma unroll
        for (int sl = 0; sl < D3DEPTH; sl++) {
            MBAR_INIT(MB_DF(sl), 4);
            MBAR_INIT(MB_DE(sl), 4);
        }
    }
    __syncthreads();

    const float* bias = (const float*)(sm + OFF_BIAS);
    const float* wos  = (const float*)(sm + OFF_WO);
    const float* bos  = (const float*)(sm + OFF_BO);
    const int NT = (B + 15) >> 4;
    const int bid = blockIdx.x, gsz = gridDim.x;
    int niter = (bid < NT) ? ((NT - 1 - bid) / gsz + 1) : 0;
    const uint32_t aRowOff = (uint32_t)(lane & 15);
    const int g = lane >> 2, q = lane & 3;

    if (s == 0) {
        // ---------------- stage 0: posenc + L0 + FEAT*W3B partial ----------
        int h0s = 0, h0p = 1, d3s = 0, d3p = 1;
        for (int j = 0; j < niter; j++) {
            int pbase = (bid + j*gsz) << 4;
            MBAR_WAIT(MB_HE(0, h0s), h0p);
            MBAR_WAIT(MB_DE(d3s), d3p);
            asm volatile("bar.sync 1, 128;" ::: "memory"); // FEAT reads done
            if (lane < 4) {
                int pt = 4*c + lane;
                int p = pbase + pt;
                __nv_bfloat16* fr = (__nv_bfloat16*)(sm + OFF_FEAT + pt*PW0);
                float xv0 = 0.f, xv1 = 0.f, xv2 = 0.f;
                if (p < B) { xv0 = x[3*p]; xv1 = x[3*p+1]; xv2 = x[3*p+2]; }
                fr[0] = __float2bfloat16(xv0);
                fr[1] = __float2bfloat16(xv1);
                fr[2] = __float2bfloat16(xv2);
                float s0 = sinf(xv0), c0v = cosf(xv0);
                float s1 = sinf(xv1), c1v = cosf(xv1);
                float s2 = sinf(xv2), c2v = cosf(xv2);
                #pragma unroll
                for (int b = 0; b < 10; b++) {
                    int f = 3 + b*6;
                    fr[f+0] = __float2bfloat16(s0);
                    fr[f+1] = __float2bfloat16(s1);
                    fr[f+2] = __float2bfloat16(s2);
                    fr[f+3] = __float2bfloat16(c0v);
                    fr[f+4] = __float2bfloat16(c1v);
                    fr[f+5] = __float2bfloat16(c2v);
                    float ns0 = 2.f*s0*c0v, nc0 = 2.f*c0v*c0v - 1.f;
                    float ns1 = 2.f*s1*c1v, nc1 = 2.f*c1v*c1v - 1.f;
                    float ns2 = 2.f*s2*c2v, nc2 = 2.f*c2v*c2v - 1.f;
                    s0 = ns0; c0v = nc0; s1 = ns1; c1v = nc1; s2 = ns2; c2v = nc2;
                }
                fr[63] = __float2bfloat16(0.f);
            }
            asm volatile("bar.sync 1, 128;" ::: "memory"); // FEAT visible

            float acc0[4][4], acc3[4][4];
            #pragma unroll
            for (int i = 0; i < 4; i++)
                #pragma unroll
                for (int r = 0; r < 4; r++) { acc0[i][r] = 0.f; acc3[i][r] = 0.f; }
            uint32_t aA = smb + OFF_FEAT + aRowOff*PW0 + 16u*(lane >> 4);
            #pragma unroll
            for (int kk = 0; kk < 4; kk++) {
                uint32_t a0, a1, a2, a3;
                ldsm4(a0, a1, a2, a3, aA + kk*32);
                #pragma unroll
                for (int nt = 0; nt < 4; nt++) {
                    mma16(acc0[nt], a0, a1, a2, a3, wb[kk][2*nt], wb[kk][2*nt+1]);
                    mma16(acc3[nt], a0, a1, a2, a3, wb[kk+4][2*nt], wb[kk+4][2*nt+1]);
                }
            }
            epiH(sm + OFF_H0 + h0s*HSLOT, bias + 0, acc0, lane, ncol0);
            {   // D3 fp32 partial store: [i(16)][c*32+lane]
                float* d3 = (float*)(sm + OFF_D3 + d3s*D3SLOT) + c*32 + lane;
                #pragma unroll
                for (int nt = 0; nt < 4; nt++)
                    #pragma unroll
                    for (int r = 0; r < 4; r++)
                        d3[(nt*4 + r)*128] = acc3[nt][r];
            }
            if (lane == 0) { MBAR_ARRIVE(MB_HF(0, h0s)); MBAR_ARRIVE(MB_DF(d3s)); }
            h0s ^= 1; if (!h0s) h0p ^= 1;
            if (++d3s == D3DEPTH) { d3s = 0; d3p ^= 1; }
        }
    } else if (s == 1 || s == 2) {
        // ---------------- stage 1/2: H(in) -> H(out) -----------------------
        const int rin = s - 1, rout = s;      // ring ids: H0=0, H1=1, H2=2
        const int inOff = (s == 1) ? OFF_H0 : OFF_H1;
        const int outOff = (s == 1) ? OFF_H1 : OFF_H2;
        const float* bl = bias + 128*s;
        int is = 0, ip = 0, os = 0, op = 1;
        for (int j = 0; j < niter; j++) {
            MBAR_WAIT(MB_HF(rin, is), ip);
            float acc[4][4];
            #pragma unroll
            for (int i = 0; i < 4; i++)
                #pragma unroll
                for (int r = 0; r < 4; r++) acc[i][r] = 0.f;
            uint32_t aA = smb + (uint32_t)(inOff + is*HSLOT)
                        + aRowOff*PH + 16u*(lane >> 4);
            #pragma unroll
            for (int kk = 0; kk < 8; kk++) {
                uint32_t a0, a1, a2, a3;
                ldsm4(a0, a1, a2, a3, aA + kk*32);
                #pragma unroll
                for (int nt = 0; nt < 4; nt++)
                    mma16(acc[nt], a0, a1, a2, a3, wb[kk][2*nt], wb[kk][2*nt+1]);
            }
            if (lane == 0) MBAR_ARRIVE(MB_HE(rin, is));
            is ^= 1; if (!is) ip ^= 1;
            MBAR_WAIT(MB_HE(rout, os), op);
            epiH(sm + outOff + os*HSLOT, bl, acc, lane, ncol0);
            if (lane == 0) MBAR_ARRIVE(MB_HF(rout, os));
            os ^= 1; if (!os) op ^= 1;
        }
    } else {
        // ---------------- stage 3: H2*W3A + D3 -> projection + Rodrigues ---
        float* red = (float*)(sm + OFF_RED);
        int h2s = 0, h2p = 0, d3s = 0, d3p = 0;
        for (int j = 0; j < niter; j++) {
            int pbase = (bid + j*gsz) << 4;
            // prefetch grad for Rodrigues (hide DRAM latency under GEMM)
            float gg0 = 0.f, gg1 = 0.f, gg2 = 0.f;
            int prow = 4*c + lane, pp = pbase + prow;
            if (lane < 4 && pp < B) {
                gg0 = out[B + 3*pp]; gg1 = out[B + 3*pp+1]; gg2 = out[B + 3*pp+2];
            }
            MBAR_WAIT(MB_DF(d3s), d3p);
            float acc[4][4];
            {
                const float* d3 = (const float*)(sm + OFF_D3 + d3s*D3SLOT) + c*32 + lane;
                #pragma unroll
                for (int nt = 0; nt < 4; nt++)
                    #pragma unroll
                    for (int r = 0; r < 4; r++)
                        acc[nt][r] = d3[(nt*4 + r)*128];
            }
            if (lane == 0) MBAR_ARRIVE(MB_DE(d3s));
            if (++d3s == D3DEPTH) { d3s = 0; d3p ^= 1; }

            MBAR_WAIT(MB_HF(2, h2s), h2p);
            uint32_t aA = smb + (uint32_t)(OFF_H2 + h2s*HSLOT)
                        + aRowOff*PH + 16u*(lane >> 4);
            #pragma unroll
            for (int kk = 0; kk < 8; kk++) {
                uint32_t a0, a1, a2, a3;
                ldsm4(a0, a1, a2, a3, aA + kk*32);
                #pragma unroll
                for (int nt = 0; nt < 4; nt++)
                    mma16(acc[nt], a0, a1, a2, a3, wb[kk][2*nt], wb[kk][2*nt+1]);
            }
            if (lane == 0) MBAR_ARRIVE(MB_HE(2, h2s));
            h2s ^= 1; if (!h2s) h2p ^= 1;

            // projection: bias+relu then dot with wo; rows g, g+8
            const float* b3s = bias + 384;
            float sA0 = 0.f, sA1 = 0.f, sA2 = 0.f;   // row g
            float sB0 = 0.f, sB1 = 0.f, sB2 = 0.f;   // row g+8
            #pragma unroll
            for (int nt = 0; nt < 4; nt++) {
                int n = ncol0 + nt*8 + 2*q;
                float bv0 = b3s[n], bv1 = b3s[n+1];
                float v00 = fmaxf(acc[nt][0] + bv0, 0.f);
                float v01 = fmaxf(acc[nt][1] + bv1, 0.f);
                float v10 = fmaxf(acc[nt][2] + bv0, 0.f);
                float v11 = fmaxf(acc[nt][3] + bv1, 0.f);
                const float* wp = wos + 3*n;
                float w00 = wp[0], w01 = wp[1], w02 = wp[2];
                float w10 = wp[3], w11 = wp[4], w12 = wp[5];
                sA0 += v00*w00 + v01*w10;
                sA1 += v00*w01 + v01*w11;
                sA2 += v00*w02 + v01*w12;
                sB0 += v10*w00 + v11*w10;
                sB1 += v10*w01 + v11*w11;
                sB2 += v10*w02 + v11*w12;
            }
            sA0 += __shfl_xor_sync(0xffffffff, sA0, 1);
            sA1 += __shfl_xor_sync(0xffffffff, sA1, 1);
            sA2 += __shfl_xor_sync(0xffffffff, sA2, 1);
            sB0 += __shfl_xor_sync(0xffffffff, sB0, 1);
            sB1 += __shfl_xor_sync(0xffffffff, sB1, 1);
            sB2 += __shfl_xor_sync(0xffffffff, sB2, 1);
            sA0 += __shfl_xor_sync(0xffffffff, sA0, 2);
            sA1 += __shfl_xor_sync(0xffffffff, sA1, 2);
            sA2 += __shfl_xor_sync(0xffffffff, sA2, 2);
            sB0 += __shfl_xor_sync(0xffffffff, sB0, 2);
            sB1 += __shfl_xor_sync(0xffffffff, sB1, 2);
            sB2 += __shfl_xor_sync(0xffffffff, sB2, 2);
            if (q == 0) {
                float* rp = red + (g*4 + c)*3;
                rp[0] = sA0; rp[1] = sA1; rp[2] = sA2;
                float* rp2 = red + ((g+8)*4 + c)*3;
                rp2[0] = sB0; rp2[1] = sB1; rp2[2] = sB2;
            }
            asm volatile("bar.sync 4, 128;" ::: "memory");
            if (lane < 4 && pp < B) {
                const float* rr = red + prow*12;
                float r0 = bos[0] + rr[0] + rr[3] + rr[6] + rr[9];
                float r1 = bos[1] + rr[1] + rr[4] + rr[7] + rr[10];
                float r2 = bos[2] + rr[2] + rr[5] + rr[8] + rr[11];
                float theta = sqrtf(r0*r0 + r1*r1 + r2*r2 + 1e-12f);
                float it = 1.f / theta;
                float e0 = r0*it, e1 = r1*it, e2 = r2*it;
                float a = sqrtf(gg0*gg0 + gg1*gg1 + gg2*gg2 + 1e-12f);
                float ia = 1.f / a;
                float v0 = gg0*ia, v1 = gg1*ia, v2 = gg2*ia;
                float ct = cosf(theta), st = sinf(theta);
                float cr0 = e1*v2 - e2*v1;
                float cr1 = e2*v0 - e0*v2;
                float cr2 = e0*v1 - e1*v0;
                float dt = e0*v0 + e1*v1 + e2*v2;
                float omc = (1.f - ct) * dt;
                out[4*B + 3*pp+0] = a * (ct*v0 + st*cr0 + omc*e0);
                out[4*B + 3*pp+1] = a * (ct*v1 + st*cr1 + omc*e1);
                out[4*B + 3*pp+2] = a * (ct*v2 + st*cr2 + omc*e2);
            }
            asm volatile("bar.sync 4, 128;" ::: "memory");
        }
    }
}

// ---------------------------------------------------------------------------
extern "C" void kernel_launch(void* const* d_in, const int* in_sizes, int n_in,
                              void* d_out, int out_size)
{
    const float* x    = (const float*)d_in[0];
    const float* grid = (const float*)d_in[1];
    const float* w0   = (const float*)d_in[2];
    const float* b0   = (const float*)d_in[3];
    const float* w1   = (const float*)d_in[4];
    const float* b1   = (const float*)d_in[5];
    const float* w2   = (const float*)d_in[6];
    const float* b2   = (const float*)d_in[7];
    const float* w3   = (const float*)d_in[8];
    const float* b3   = (const float*)d_in[9];
    const float* wo   = (const float*)d_in[10];
    const float* bo   = (const float*)d_in[11];
    float* out = (float*)d_out;
    int B = in_sizes[0] / 3;

    gather_kernel<<<(B + 255) / 256, 256>>>(x, grid, out, B);

    int nsm = 148;
    cudaDeviceGetAttribute(&nsm, cudaDevAttrMultiProcessorCount, 0);
    cudaFuncSetAttribute(mlp_kernel,
                         cudaFuncAttributeMaxDynamicSharedMemorySize, SMEM_BYTES);
    mlp_kernel<<<nsm, 512, SMEM_BYTES>>>(x, w0, b0, w1, b1, w2, b2,
                                         w3, b3, wo, bo, out, B);
}